// round 1
// baseline (speedup 1.0000x reference)
#include <cuda_runtime.h>
#include <math.h>

#define EMBED 1024
#define NHEAD 16
#define HD 64
#define BATCH 2
#define SQ 2048
#define SKV 2048
#define MTOT (BATCH*SQ)   // 4096 rows for projection GEMMs

// ---- scratch (static device globals; no allocation at runtime) ----
__device__ float g_q [(size_t)MTOT * EMBED];
__device__ float g_k [(size_t)BATCH * SKV * EMBED];
__device__ float g_v [(size_t)BATCH * SKV * EMBED];
__device__ float g_ao[(size_t)MTOT * EMBED];

// ============================================================================
// Y[M,N] = X[M,K] @ W[N,K]^T   (torch Linear: y = x @ W.T, W row-major [N,K])
// 64x64 block tile, K-tile 16, 256 threads, 4x4 register micro-tile.
// Requires M%64==0, N%64==0, K%16==0 (true for all calls here).
// ============================================================================
__global__ void gemm_nt_kernel(const float* __restrict__ X,
                               const float* __restrict__ W,
                               float* __restrict__ Y,
                               int M, int N, int K)
{
    __shared__ float sX[16][65];   // [k][m], padded -> conflict-free
    __shared__ float sW[16][65];   // [k][n]

    const int tx = threadIdx.x & 15;
    const int ty = threadIdx.x >> 4;
    const int m0 = blockIdx.y * 64;
    const int n0 = blockIdx.x * 64;

    const int lk = threadIdx.x & 15;   // k within tile for loading
    const int lm = threadIdx.x >> 4;   // base row for loading

    float acc[4][4] = {};

    for (int k0 = 0; k0 < K; k0 += 16) {
        #pragma unroll
        for (int i = 0; i < 4; i++) {
            int m = lm + i * 16;
            sX[lk][m] = X[(size_t)(m0 + m) * K + k0 + lk];
            sW[lk][m] = W[(size_t)(n0 + m) * K + k0 + lk];
        }
        __syncthreads();

        #pragma unroll
        for (int k = 0; k < 16; k++) {
            float a[4], b[4];
            #pragma unroll
            for (int i = 0; i < 4; i++) a[i] = sX[k][ty * 4 + i];
            #pragma unroll
            for (int j = 0; j < 4; j++) b[j] = sW[k][tx * 4 + j];
            #pragma unroll
            for (int i = 0; i < 4; i++)
                #pragma unroll
                for (int j = 0; j < 4; j++)
                    acc[i][j] = fmaf(a[i], b[j], acc[i][j]);
        }
        __syncthreads();
    }

    #pragma unroll
    for (int i = 0; i < 4; i++) {
        int m = m0 + ty * 4 + i;
        #pragma unroll
        for (int j = 0; j < 4; j++)
            Y[(size_t)m * N + n0 + tx * 4 + j] = acc[i][j];
    }
}

// ============================================================================
// Flash-style attention (fp32, online softmax).
// Grid: (SQ/64, NHEAD, BATCH); Block: 256 threads (16x16).
// Q/K/V are the projected [B, S, EMBED] buffers; head h = columns [h*64, h*64+64).
// Out is written as [B, SQ, EMBED] (heads concatenated) for the final GEMM.
// Dynamic smem layout (floats):
//   sQ [64][65]  (transposed: [d][r], pre-scaled by 1/sqrt(HD))
//   sK [64][65]  (transposed: [d][c])
//   sV [64][64]  ([c][d])
//   sP [64][65]  ([r][c])
//   sB [64]
// ============================================================================
#define ATTN_SMEM_FLOATS (64*65 + 64*65 + 64*64 + 64*65 + 64)
#define ATTN_SMEM_BYTES  (ATTN_SMEM_FLOATS * 4)

__global__ void attn_kernel(const float* __restrict__ Q,
                            const float* __restrict__ K,
                            const float* __restrict__ V,
                            const float* __restrict__ bias,
                            float* __restrict__ Out)
{
    extern __shared__ float sm[];
    float* sQ = sm;                  // 64*65
    float* sK = sQ + 64 * 65;        // 64*65
    float* sV = sK + 64 * 65;        // 64*64
    float* sP = sV + 64 * 64;        // 64*65
    float* sB = sP + 64 * 65;        // 64

    const int tid = threadIdx.x;
    const int tx  = tid & 15;
    const int ty  = tid >> 4;
    const int qb  = blockIdx.x;
    const int h   = blockIdx.y;
    const int b   = blockIdx.z;

    const float* Qb = Q + ((size_t)(b * SQ + qb * 64)) * EMBED + h * HD;
    const float* Kb = K + (size_t)b * SKV * EMBED + h * HD;
    const float* Vb = V + (size_t)b * SKV * EMBED + h * HD;
    const float* Bb = bias + (size_t)b * SKV;

    const float scale = 0.125f;   // 1/sqrt(64)
    const int ld = tid & 63;      // load: d index
    const int lr = tid >> 6;      // load: row base (0..3)

    // Load Q tile transposed & pre-scaled: sQ[d][r]
    #pragma unroll
    for (int p = 0; p < 16; p++) {
        int r = lr + p * 4;
        sQ[ld * 65 + r] = Qb[(size_t)r * EMBED + ld] * scale;
    }

    float mrow[4], lrow[4], o[4][4];
    #pragma unroll
    for (int i = 0; i < 4; i++) {
        mrow[i] = -INFINITY;
        lrow[i] = 0.0f;
        #pragma unroll
        for (int j = 0; j < 4; j++) o[i][j] = 0.0f;
    }

    for (int kt = 0; kt < SKV / 64; kt++) {
        __syncthreads();   // previous iteration done reading sK/sV
        // Load K (transposed) and V tiles, bias
        #pragma unroll
        for (int p = 0; p < 16; p++) {
            int c = lr + p * 4;
            float kv = Kb[(size_t)(kt * 64 + c) * EMBED + ld];
            float vv = Vb[(size_t)(kt * 64 + c) * EMBED + ld];
            sK[ld * 65 + c] = kv;
            sV[c * 64 + ld] = vv;
        }
        if (tid < 64) sB[tid] = Bb[kt * 64 + tid];
        __syncthreads();

        // S = Qs @ K^T + bias  (4x4 per thread: rows ty*4+i, cols tx*4+j)
        float s[4][4] = {};
        #pragma unroll
        for (int d = 0; d < 64; d++) {
            float a[4], bb[4];
            #pragma unroll
            for (int i = 0; i < 4; i++) a[i]  = sQ[d * 65 + ty * 4 + i];
            #pragma unroll
            for (int j = 0; j < 4; j++) bb[j] = sK[d * 65 + tx * 4 + j];
            #pragma unroll
            for (int i = 0; i < 4; i++)
                #pragma unroll
                for (int j = 0; j < 4; j++)
                    s[i][j] = fmaf(a[i], bb[j], s[i][j]);
        }
        #pragma unroll
        for (int j = 0; j < 4; j++) {
            float bv = sB[tx * 4 + j];
            #pragma unroll
            for (int i = 0; i < 4; i++) s[i][j] += bv;
        }

        // Online softmax per row (rows distributed by ty; cols across 16 tx
        // lanes, which live in one 16-lane half of the warp -> xor-shuffles
        // with masks 1,2,4,8 reduce exactly across tx).
        #pragma unroll
        for (int i = 0; i < 4; i++) {
            float mt = fmaxf(fmaxf(s[i][0], s[i][1]), fmaxf(s[i][2], s[i][3]));
            #pragma unroll
            for (int msk = 8; msk >= 1; msk >>= 1)
                mt = fmaxf(mt, __shfl_xor_sync(0xffffffffu, mt, msk));
            float mn = fmaxf(mrow[i], mt);
            float corr = __expf(mrow[i] - mn);
            mrow[i] = mn;
            lrow[i] *= corr;
            #pragma unroll
            for (int j = 0; j < 4; j++) o[i][j] *= corr;

            float ps = 0.0f;
            #pragma unroll
            for (int j = 0; j < 4; j++) {
                float p = __expf(s[i][j] - mn);
                s[i][j] = p;
                ps += p;
            }
            #pragma unroll
            for (int msk = 8; msk >= 1; msk >>= 1)
                ps += __shfl_xor_sync(0xffffffffu, ps, msk);
            lrow[i] += ps;

            #pragma unroll
            for (int j = 0; j < 4; j++)
                sP[(ty * 4 + i) * 65 + tx * 4 + j] = s[i][j];
        }
        __syncthreads();

        // O += P @ V  (4x4 per thread: rows ty*4+i, dims tx*4+j)
        #pragma unroll
        for (int c = 0; c < 64; c++) {
            float a[4], bb[4];
            #pragma unroll
            for (int i = 0; i < 4; i++) a[i]  = sP[(ty * 4 + i) * 65 + c];
            #pragma unroll
            for (int j = 0; j < 4; j++) bb[j] = sV[c * 64 + tx * 4 + j];
            #pragma unroll
            for (int i = 0; i < 4; i++)
                #pragma unroll
                for (int j = 0; j < 4; j++)
                    o[i][j] = fmaf(a[i], bb[j], o[i][j]);
        }
    }

    // Normalize and write out (heads concatenated)
    #pragma unroll
    for (int i = 0; i < 4; i++) {
        float inv = 1.0f / lrow[i];
        size_t row = (size_t)(b * SQ + qb * 64 + ty * 4 + i);
        #pragma unroll
        for (int j = 0; j < 4; j++)
            Out[row * EMBED + h * HD + tx * 4 + j] = o[i][j] * inv;
    }
}

// ============================================================================
extern "C" void kernel_launch(void* const* d_in, const int* in_sizes, int n_in,
                              void* d_out, int out_size)
{
    const float* q    = (const float*)d_in[0];
    const float* k    = (const float*)d_in[1];
    const float* v    = (const float*)d_in[2];
    const float* bias = (const float*)d_in[3];
    const float* Wq   = (const float*)d_in[4];
    const float* Wk   = (const float*)d_in[5];
    const float* Wv   = (const float*)d_in[6];
    const float* Wo   = (const float*)d_in[7];
    float* out = (float*)d_out;

    float *gq, *gk, *gv, *gao;
    cudaGetSymbolAddress((void**)&gq,  g_q);
    cudaGetSymbolAddress((void**)&gk,  g_k);
    cudaGetSymbolAddress((void**)&gv,  g_v);
    cudaGetSymbolAddress((void**)&gao, g_ao);

    cudaFuncSetAttribute(attn_kernel,
                         cudaFuncAttributeMaxDynamicSharedMemorySize,
                         ATTN_SMEM_BYTES);

    dim3 gp(EMBED / 64, MTOT / 64);   // (16, 64)

    // Projections
    gemm_nt_kernel<<<gp, 256>>>(q, Wq, gq, MTOT, EMBED, EMBED);
    gemm_nt_kernel<<<gp, 256>>>(k, Wk, gk, MTOT, EMBED, EMBED);
    gemm_nt_kernel<<<gp, 256>>>(v, Wv, gv, MTOT, EMBED, EMBED);

    // Attention
    dim3 ga(SQ / 64, NHEAD, BATCH);   // (32, 16, 2)
    attn_kernel<<<ga, 256, ATTN_SMEM_BYTES>>>(gq, gk, gv, bias, gao);

    // Output projection
    gemm_nt_kernel<<<gp, 256>>>(gao, Wo, out, MTOT, EMBED, EMBED);
}

// round 4
// speedup vs baseline: 1.7018x; 1.7018x over previous
#include <cuda_runtime.h>
#include <cuda_bf16.h>
#include <math.h>
#include <stdint.h>

#define EMBED 1024
#define NHEAD 16
#define HD 64
#define BATCH 2
#define SQ 2048
#define SKV 2048
#define MTOT (BATCH*SQ)

#define NACT ((size_t)MTOT * EMBED)
#define NWEI ((size_t)EMBED * EMBED)

// ---- fp32 scratch ----
__device__ __align__(16) float g_q[(size_t)MTOT * EMBED];
__device__ __align__(16) float g_k[(size_t)BATCH * SKV * EMBED];
__device__ __align__(16) float g_v[(size_t)BATCH * SKV * EMBED];
__device__ __align__(16) float g_ao[(size_t)MTOT * EMBED];

// ---- bf16 hi/lo split scratch ----
__device__ __align__(16) __nv_bfloat16 g_xq_hi[NACT];
__device__ __align__(16) __nv_bfloat16 g_xq_lo[NACT];
__device__ __align__(16) __nv_bfloat16 g_xk_hi[NACT];
__device__ __align__(16) __nv_bfloat16 g_xk_lo[NACT];
__device__ __align__(16) __nv_bfloat16 g_xv_hi[NACT];
__device__ __align__(16) __nv_bfloat16 g_xv_lo[NACT];
__device__ __align__(16) __nv_bfloat16 g_ao_hi[NACT];
__device__ __align__(16) __nv_bfloat16 g_ao_lo[NACT];
__device__ __align__(16) __nv_bfloat16 g_wq_hi[NWEI];
__device__ __align__(16) __nv_bfloat16 g_wq_lo[NWEI];
__device__ __align__(16) __nv_bfloat16 g_wk_hi[NWEI];
__device__ __align__(16) __nv_bfloat16 g_wk_lo[NWEI];
__device__ __align__(16) __nv_bfloat16 g_wv_hi[NWEI];
__device__ __align__(16) __nv_bfloat16 g_wv_lo[NWEI];
__device__ __align__(16) __nv_bfloat16 g_wo_hi[NWEI];
__device__ __align__(16) __nv_bfloat16 g_wo_lo[NWEI];

// ============================================================================
// fp32 -> bf16 hi/lo split: x = hi + lo + O(2^-16). 4 elements per thread.
// ============================================================================
__global__ void split_bf16_kernel(const float* __restrict__ x,
                                  __nv_bfloat16* __restrict__ hi,
                                  __nv_bfloat16* __restrict__ lo,
                                  int n)
{
    int i = (blockIdx.x * blockDim.x + threadIdx.x) * 4;
    if (i >= n) return;
    float4 v = *reinterpret_cast<const float4*>(x + i);
    __nv_bfloat16 h0 = __float2bfloat16(v.x);
    __nv_bfloat16 h1 = __float2bfloat16(v.y);
    __nv_bfloat16 h2 = __float2bfloat16(v.z);
    __nv_bfloat16 h3 = __float2bfloat16(v.w);
    __nv_bfloat16 l0 = __float2bfloat16(v.x - __bfloat162float(h0));
    __nv_bfloat16 l1 = __float2bfloat16(v.y - __bfloat162float(h1));
    __nv_bfloat16 l2 = __float2bfloat16(v.z - __bfloat162float(h2));
    __nv_bfloat16 l3 = __float2bfloat16(v.w - __bfloat162float(h3));
    __nv_bfloat162* hp = reinterpret_cast<__nv_bfloat162*>(hi + i);
    __nv_bfloat162* lp = reinterpret_cast<__nv_bfloat162*>(lo + i);
    hp[0] = __halves2bfloat162(h0, h1);
    hp[1] = __halves2bfloat162(h2, h3);
    lp[0] = __halves2bfloat162(l0, l1);
    lp[1] = __halves2bfloat162(l2, l3);
}

// ============================================================================
// MMA helpers
// ============================================================================
__device__ __forceinline__ void cp16(uint32_t dst, const void* src)
{
    asm volatile("cp.async.cg.shared.global [%0], [%1], 16;\n" :: "r"(dst), "l"(src));
}
__device__ __forceinline__ void cp_commit()
{
    asm volatile("cp.async.commit_group;\n" ::: "memory");
}
__device__ __forceinline__ void cp_wait0()
{
    asm volatile("cp.async.wait_group 0;\n" ::: "memory");
}
__device__ __forceinline__ void ldsm4(uint32_t* r, uint32_t addr)
{
    asm volatile("ldmatrix.sync.aligned.m8n8.x4.shared.b16 {%0,%1,%2,%3}, [%4];\n"
                 : "=r"(r[0]), "=r"(r[1]), "=r"(r[2]), "=r"(r[3]) : "r"(addr));
}
__device__ __forceinline__ void mma16816(float* c, const uint32_t* a, uint32_t b0, uint32_t b1)
{
    asm volatile("mma.sync.aligned.m16n8k16.row.col.f32.bf16.bf16.f32 "
                 "{%0,%1,%2,%3},{%4,%5,%6,%7},{%8,%9},{%0,%1,%2,%3};\n"
                 : "+f"(c[0]), "+f"(c[1]), "+f"(c[2]), "+f"(c[3])
                 : "r"(a[0]), "r"(a[1]), "r"(a[2]), "r"(a[3]), "r"(b0), "r"(b1));
}

// ============================================================================
// Y[M,N] = X[M,K] @ W[N,K]^T via bf16 hi/lo split MMA.
// BM=128, BN=64, BK=32; 256 threads = 8 warps (4m x 2n), warp tile 32x32.
// smem rows padded to 40 bf16 (80B).
// ============================================================================
#define GBM 128
#define GBN 64
#define GBK 32
#define GPADS 40

#define OFF_AHI 0
#define OFF_ALO (GBM*GPADS)
#define OFF_BHI (2*GBM*GPADS)
#define OFF_BLO (2*GBM*GPADS + GBN*GPADS)
#define STAGE_ELEMS (2*GBM*GPADS + 2*GBN*GPADS)
#define GEMM_SMEM_BYTES (STAGE_ELEMS * 2 * 2)

__device__ __forceinline__ void gemm_load_stage(uint32_t sbase, int t, int m0, int n0,
                                                int k0, int K,
                                                const __nv_bfloat16* Ahi,
                                                const __nv_bfloat16* Alo,
                                                const __nv_bfloat16* Bhi,
                                                const __nv_bfloat16* Blo)
{
    int r0 = t >> 2;
    int c0 = (t & 3) * 8;
    size_t ga0 = (size_t)(m0 + r0) * K + k0 + c0;
    uint32_t sa0 = (uint32_t)((r0 * GPADS + c0) * 2);
    cp16(sbase + OFF_AHI * 2 + sa0, Ahi + ga0);
    cp16(sbase + OFF_ALO * 2 + sa0, Alo + ga0);
    size_t ga1 = (size_t)(m0 + 64 + r0) * K + k0 + c0;
    uint32_t sa1 = (uint32_t)(((64 + r0) * GPADS + c0) * 2);
    cp16(sbase + OFF_AHI * 2 + sa1, Ahi + ga1);
    cp16(sbase + OFF_ALO * 2 + sa1, Alo + ga1);
    int rb = r0 & 63;
    size_t gb = (size_t)(n0 + rb) * K + k0 + c0;
    uint32_t sb = (uint32_t)((rb * GPADS + c0) * 2);
    cp16(sbase + OFF_BHI * 2 + sb, Bhi + gb);
    cp16(sbase + OFF_BLO * 2 + sb, Blo + gb);
}

__global__ void __launch_bounds__(256)
gemm_nt_bf16s_kernel(const __nv_bfloat16* __restrict__ Ahi,
                     const __nv_bfloat16* __restrict__ Alo,
                     const __nv_bfloat16* __restrict__ Bhi,
                     const __nv_bfloat16* __restrict__ Blo,
                     float* __restrict__ Y,
                     int M, int N, int K)
{
    extern __shared__ __nv_bfloat16 smem[];
    const uint32_t smem_base = (uint32_t)__cvta_generic_to_shared(smem);

    const int t    = threadIdx.x;
    const int lane = t & 31;
    const int wid  = t >> 5;
    const int wm   = wid & 3;
    const int wn   = wid >> 2;
    const int m0   = blockIdx.y * GBM;
    const int n0   = blockIdx.x * GBN;

    float acc[2][4][4];
    #pragma unroll
    for (int i = 0; i < 2; i++) {
        #pragma unroll
        for (int j = 0; j < 4; j++) {
            #pragma unroll
            for (int l = 0; l < 4; l++) {
                acc[i][j][l] = 0.0f;
            }
        }
    }

    gemm_load_stage(smem_base, t, m0, n0, 0, K, Ahi, Alo, Bhi, Blo);
    cp_commit();

    const int NIT = K / GBK;
    for (int it = 0; it < NIT; it++) {
        cp_wait0();
        __syncthreads();
        int cur = it & 1;
        if (it + 1 < NIT) {
            gemm_load_stage(smem_base + (uint32_t)((cur ^ 1) * STAGE_ELEMS * 2),
                            t, m0, n0, (it + 1) * GBK, K, Ahi, Alo, Bhi, Blo);
            cp_commit();
        }

        uint32_t sbase = smem_base + (uint32_t)(cur * STAGE_ELEMS * 2);

        #pragma unroll
        for (int ksub = 0; ksub < 2; ksub++) {
            uint32_t ahi[2][4];
            uint32_t alo[2][4];
            #pragma unroll
            for (int mt = 0; mt < 2; mt++) {
                int row = wm * 32 + mt * 16 + (lane & 15);
                uint32_t koff = (uint32_t)(((lane >> 4) * 16) + ksub * 32);
                ldsm4(ahi[mt], sbase + (uint32_t)((OFF_AHI + row * GPADS) * 2) + koff);
                ldsm4(alo[mt], sbase + (uint32_t)((OFF_ALO + row * GPADS) * 2) + koff);
            }
            uint32_t bhi[2][4];
            uint32_t blo[2][4];
            #pragma unroll
            for (int np = 0; np < 2; np++) {
                int row = wn * 32 + np * 16 + (((lane >> 4) << 3) | (lane & 7));
                uint32_t koff = (uint32_t)((((lane >> 3) & 1) * 16) + ksub * 32);
                ldsm4(bhi[np], sbase + (uint32_t)((OFF_BHI + row * GPADS) * 2) + koff);
                ldsm4(blo[np], sbase + (uint32_t)((OFF_BLO + row * GPADS) * 2) + koff);
            }
            #pragma unroll
            for (int mt = 0; mt < 2; mt++) {
                #pragma unroll
                for (int nt = 0; nt < 4; nt++) {
                    int np = nt >> 1;
                    int h  = (nt & 1) * 2;
                    mma16816(acc[mt][nt], ahi[mt], bhi[np][h], bhi[np][h + 1]);
                    mma16816(acc[mt][nt], ahi[mt], blo[np][h], blo[np][h + 1]);
                    mma16816(acc[mt][nt], alo[mt], bhi[np][h], bhi[np][h + 1]);
                }
            }
        }
        __syncthreads();
    }

    #pragma unroll
    for (int mt = 0; mt < 2; mt++) {
        #pragma unroll
        for (int nt = 0; nt < 4; nt++) {
            int row = m0 + wm * 32 + mt * 16 + (lane >> 2);
            int col = n0 + wn * 32 + nt * 8 + (lane & 3) * 2;
            Y[(size_t)row * N + col]           = acc[mt][nt][0];
            Y[(size_t)row * N + col + 1]       = acc[mt][nt][1];
            Y[(size_t)(row + 8) * N + col]     = acc[mt][nt][2];
            Y[(size_t)(row + 8) * N + col + 1] = acc[mt][nt][3];
        }
    }
}

// ============================================================================
// fast exp on the FMA pipe (no MUFU). Inputs are <= 0; clamped at -87.
// ============================================================================
__device__ __forceinline__ float fast_exp(float x)
{
    x = fmaxf(x, -87.0f);
    float y  = x * 1.4426950408889634f;
    float nf = y + 12582912.0f;
    float n  = nf - 12582912.0f;
    float f  = y - n;
    float p  = 1.3333558146e-3f;
    p = fmaf(p, f, 9.6181291076e-3f);
    p = fmaf(p, f, 5.5504108664e-2f);
    p = fmaf(p, f, 2.4022650696e-1f);
    p = fmaf(p, f, 6.9314718056e-1f);
    p = fmaf(p, f, 1.0f);
    int i = __float_as_int(nf) - 0x4B400000;
    float s = __int_as_float((i + 127) << 23);
    return p * s;
}

// ============================================================================
// Flash-style attention (fp32, online softmax), exp on FMA pipe.
// ============================================================================
#define ATTN_SMEM_FLOATS (64*65 + 64*65 + 64*64 + 64*65 + 64)
#define ATTN_SMEM_BYTES  (ATTN_SMEM_FLOATS * 4)

__global__ void attn_kernel(const float* __restrict__ Q,
                            const float* __restrict__ K,
                            const float* __restrict__ V,
                            const float* __restrict__ bias,
                            float* __restrict__ Out)
{
    extern __shared__ float sm[];
    float* sQ = sm;
    float* sK = sQ + 64 * 65;
    float* sV = sK + 64 * 65;
    float* sP = sV + 64 * 64;
    float* sB = sP + 64 * 65;

    const int tid = threadIdx.x;
    const int tx  = tid & 15;
    const int ty  = tid >> 4;
    const int qb  = blockIdx.x;
    const int h   = blockIdx.y;
    const int b   = blockIdx.z;

    const float* Qb = Q + ((size_t)(b * SQ + qb * 64)) * EMBED + h * HD;
    const float* Kb = K + (size_t)b * SKV * EMBED + h * HD;
    const float* Vb = V + (size_t)b * SKV * EMBED + h * HD;
    const float* Bb = bias + (size_t)b * SKV;

    const float scale = 0.125f;
    const int ld = tid & 63;
    const int lr = tid >> 6;

    #pragma unroll
    for (int p = 0; p < 16; p++) {
        int r = lr + p * 4;
        sQ[ld * 65 + r] = Qb[(size_t)r * EMBED + ld] * scale;
    }

    float mrow[4];
    float lrow[4];
    float o[4][4];
    #pragma unroll
    for (int i = 0; i < 4; i++) {
        mrow[i] = -INFINITY;
        lrow[i] = 0.0f;
        #pragma unroll
        for (int j = 0; j < 4; j++) {
            o[i][j] = 0.0f;
        }
    }

    for (int kt = 0; kt < SKV / 64; kt++) {
        __syncthreads();
        #pragma unroll
        for (int p = 0; p < 16; p++) {
            int c = lr + p * 4;
            float kv = Kb[(size_t)(kt * 64 + c) * EMBED + ld];
            float vv = Vb[(size_t)(kt * 64 + c) * EMBED + ld];
            sK[ld * 65 + c] = kv;
            sV[c * 64 + ld] = vv;
        }
        if (tid < 64) {
            sB[tid] = Bb[kt * 64 + tid];
        }
        __syncthreads();

        float s[4][4];
        #pragma unroll
        for (int i = 0; i < 4; i++) {
            #pragma unroll
            for (int j = 0; j < 4; j++) {
                s[i][j] = 0.0f;
            }
        }
        #pragma unroll
        for (int d = 0; d < 64; d++) {
            float a[4];
            float bb[4];
            #pragma unroll
            for (int i = 0; i < 4; i++) { a[i]  = sQ[d * 65 + ty * 4 + i]; }
            #pragma unroll
            for (int j = 0; j < 4; j++) { bb[j] = sK[d * 65 + tx * 4 + j]; }
            #pragma unroll
            for (int i = 0; i < 4; i++) {
                #pragma unroll
                for (int j = 0; j < 4; j++) {
                    s[i][j] = fmaf(a[i], bb[j], s[i][j]);
                }
            }
        }
        #pragma unroll
        for (int j = 0; j < 4; j++) {
            float bv = sB[tx * 4 + j];
            #pragma unroll
            for (int i = 0; i < 4; i++) {
                s[i][j] += bv;
            }
        }

        #pragma unroll
        for (int i = 0; i < 4; i++) {
            float mt = fmaxf(fmaxf(s[i][0], s[i][1]), fmaxf(s[i][2], s[i][3]));
            #pragma unroll
            for (int msk = 8; msk >= 1; msk >>= 1) {
                mt = fmaxf(mt, __shfl_xor_sync(0xffffffffu, mt, msk));
            }
            float mn = fmaxf(mrow[i], mt);
            float corr = fast_exp(mrow[i] - mn);
            mrow[i] = mn;
            lrow[i] *= corr;
            #pragma unroll
            for (int j = 0; j < 4; j++) {
                o[i][j] *= corr;
            }

            float ps = 0.0f;
            #pragma unroll
            for (int j = 0; j < 4; j++) {
                float pv = fast_exp(s[i][j] - mn);
                s[i][j] = pv;
                ps += pv;
            }
            #pragma unroll
            for (int msk = 8; msk >= 1; msk >>= 1) {
                ps += __shfl_xor_sync(0xffffffffu, ps, msk);
            }
            lrow[i] += ps;

            #pragma unroll
            for (int j = 0; j < 4; j++) {
                sP[(ty * 4 + i) * 65 + tx * 4 + j] = s[i][j];
            }
        }
        __syncthreads();

        #pragma unroll
        for (int c = 0; c < 64; c++) {
            float a[4];
            float bb[4];
            #pragma unroll
            for (int i = 0; i < 4; i++) { a[i]  = sP[(ty * 4 + i) * 65 + c]; }
            #pragma unroll
            for (int j = 0; j < 4; j++) { bb[j] = sV[c * 64 + tx * 4 + j]; }
            #pragma unroll
            for (int i = 0; i < 4; i++) {
                #pragma unroll
                for (int j = 0; j < 4; j++) {
                    o[i][j] = fmaf(a[i], bb[j], o[i][j]);
                }
            }
        }
    }

    #pragma unroll
    for (int i = 0; i < 4; i++) {
        float inv = 1.0f / lrow[i];
        size_t row = (size_t)(b * SQ + qb * 64 + ty * 4 + i);
        #pragma unroll
        for (int j = 0; j < 4; j++) {
            Out[row * EMBED + h * HD + tx * 4 + j] = o[i][j] * inv;
        }
    }
}

// ============================================================================
extern "C" void kernel_launch(void* const* d_in, const int* in_sizes, int n_in,
                              void* d_out, int out_size)
{
    const float* q    = (const float*)d_in[0];
    const float* k    = (const float*)d_in[1];
    const float* v    = (const float*)d_in[2];
    const float* bias = (const float*)d_in[3];
    const float* Wq   = (const float*)d_in[4];
    const float* Wk   = (const float*)d_in[5];
    const float* Wv   = (const float*)d_in[6];
    const float* Wo   = (const float*)d_in[7];
    float* out = (float*)d_out;

    float* gq = 0;
    float* gk = 0;
    float* gv = 0;
    float* gao = 0;
    cudaGetSymbolAddress((void**)&gq,  g_q);
    cudaGetSymbolAddress((void**)&gk,  g_k);
    cudaGetSymbolAddress((void**)&gv,  g_v);
    cudaGetSymbolAddress((void**)&gao, g_ao);

    __nv_bfloat16* xqh = 0;
    __nv_bfloat16* xql = 0;
    __nv_bfloat16* xkh = 0;
    __nv_bfloat16* xkl = 0;
    __nv_bfloat16* xvh = 0;
    __nv_bfloat16* xvl = 0;
    __nv_bfloat16* aoh = 0;
    __nv_bfloat16* aol = 0;
    __nv_bfloat16* wqh = 0;
    __nv_bfloat16* wql = 0;
    __nv_bfloat16* wkh = 0;
    __nv_bfloat16* wkl = 0;
    __nv_bfloat16* wvh = 0;
    __nv_bfloat16* wvl = 0;
    __nv_bfloat16* woh = 0;
    __nv_bfloat16* wol = 0;
    cudaGetSymbolAddress((void**)&xqh, g_xq_hi);
    cudaGetSymbolAddress((void**)&xql, g_xq_lo);
    cudaGetSymbolAddress((void**)&xkh, g_xk_hi);
    cudaGetSymbolAddress((void**)&xkl, g_xk_lo);
    cudaGetSymbolAddress((void**)&xvh, g_xv_hi);
    cudaGetSymbolAddress((void**)&xvl, g_xv_lo);
    cudaGetSymbolAddress((void**)&aoh, g_ao_hi);
    cudaGetSymbolAddress((void**)&aol, g_ao_lo);
    cudaGetSymbolAddress((void**)&wqh, g_wq_hi);
    cudaGetSymbolAddress((void**)&wql, g_wq_lo);
    cudaGetSymbolAddress((void**)&wkh, g_wk_hi);
    cudaGetSymbolAddress((void**)&wkl, g_wk_lo);
    cudaGetSymbolAddress((void**)&wvh, g_wv_hi);
    cudaGetSymbolAddress((void**)&wvl, g_wv_lo);
    cudaGetSymbolAddress((void**)&woh, g_wo_hi);
    cudaGetSymbolAddress((void**)&wol, g_wo_lo);

    cudaFuncSetAttribute(attn_kernel, cudaFuncAttributeMaxDynamicSharedMemorySize,
                         ATTN_SMEM_BYTES);
    cudaFuncSetAttribute(gemm_nt_bf16s_kernel, cudaFuncAttributeMaxDynamicSharedMemorySize,
                         GEMM_SMEM_BYTES);

    int actN = (int)NACT;
    int weiN = (int)NWEI;
    int actBlocks = actN / 4 / 256;
    int weiBlocks = weiN / 4 / 256;

    split_bf16_kernel<<<actBlocks, 256>>>(q, xqh, xql, actN);
    split_bf16_kernel<<<actBlocks, 256>>>(k, xkh, xkl, actN);
    split_bf16_kernel<<<actBlocks, 256>>>(v, xvh, xvl, actN);
    split_bf16_kernel<<<weiBlocks, 256>>>(Wq, wqh, wql, weiN);
    split_bf16_kernel<<<weiBlocks, 256>>>(Wk, wkh, wkl, weiN);
    split_bf16_kernel<<<weiBlocks, 256>>>(Wv, wvh, wvl, weiN);
    split_bf16_kernel<<<weiBlocks, 256>>>(Wo, woh, wol, weiN);

    dim3 gp(EMBED / GBN, MTOT / GBM);
    gemm_nt_bf16s_kernel<<<gp, 256, GEMM_SMEM_BYTES>>>(xqh, xql, wqh, wql, gq, MTOT, EMBED, EMBED);
    gemm_nt_bf16s_kernel<<<gp, 256, GEMM_SMEM_BYTES>>>(xkh, xkl, wkh, wkl, gk, MTOT, EMBED, EMBED);
    gemm_nt_bf16s_kernel<<<gp, 256, GEMM_SMEM_BYTES>>>(xvh, xvl, wvh, wvl, gv, MTOT, EMBED, EMBED);

    dim3 ga(SQ / 64, NHEAD, BATCH);
    attn_kernel<<<ga, 256, ATTN_SMEM_BYTES>>>(gq, gk, gv, bias, gao);

    split_bf16_kernel<<<actBlocks, 256>>>(gao, aoh, aol, actN);
    gemm_nt_bf16s_kernel<<<gp, 256, GEMM_SMEM_BYTES>>>(aoh, aol, woh, wol, out, MTOT, EMBED, EMBED);
}

// round 6
// speedup vs baseline: 2.6855x; 1.5780x over previous
#include <cuda_runtime.h>
#include <cuda_bf16.h>
#include <math.h>
#include <stdint.h>

#define EMBED 1024
#define NHEAD 16
#define HD 64
#define BATCH 2
#define SQ 2048
#define SKV 2048
#define MTOT (BATCH*SQ)

#define NACT ((size_t)MTOT * EMBED)
#define NWEI ((size_t)EMBED * EMBED)

// ---- bf16 hi/lo split scratch ----
__device__ __align__(16) __nv_bfloat16 g_xq_hi[NACT];
__device__ __align__(16) __nv_bfloat16 g_xq_lo[NACT];
__device__ __align__(16) __nv_bfloat16 g_xk_hi[NACT];
__device__ __align__(16) __nv_bfloat16 g_xk_lo[NACT];
__device__ __align__(16) __nv_bfloat16 g_xv_hi[NACT];
__device__ __align__(16) __nv_bfloat16 g_xv_lo[NACT];
__device__ __align__(16) __nv_bfloat16 g_wq_hi[NWEI];
__device__ __align__(16) __nv_bfloat16 g_wq_lo[NWEI];
__device__ __align__(16) __nv_bfloat16 g_wk_hi[NWEI];
__device__ __align__(16) __nv_bfloat16 g_wk_lo[NWEI];
__device__ __align__(16) __nv_bfloat16 g_wv_hi[NWEI];
__device__ __align__(16) __nv_bfloat16 g_wv_lo[NWEI];
__device__ __align__(16) __nv_bfloat16 g_wo_hi[NWEI];
__device__ __align__(16) __nv_bfloat16 g_wo_lo[NWEI];
__device__ __align__(16) __nv_bfloat16 g_pq_hi[NACT];
__device__ __align__(16) __nv_bfloat16 g_pq_lo[NACT];
__device__ __align__(16) __nv_bfloat16 g_pk_hi[NACT];
__device__ __align__(16) __nv_bfloat16 g_pk_lo[NACT];
__device__ __align__(16) __nv_bfloat16 g_pv_hi[NACT];
__device__ __align__(16) __nv_bfloat16 g_pv_lo[NACT];
__device__ __align__(16) __nv_bfloat16 g_ao_hi[NACT];
__device__ __align__(16) __nv_bfloat16 g_ao_lo[NACT];

// ============================================================================
// fp32 -> bf16 hi/lo split: x = hi + lo + O(2^-16). 4 elements per thread.
// ============================================================================
__global__ void split_bf16_kernel(const float* __restrict__ x,
                                  __nv_bfloat16* __restrict__ hi,
                                  __nv_bfloat16* __restrict__ lo,
                                  int n)
{
    int i = (blockIdx.x * blockDim.x + threadIdx.x) * 4;
    if (i >= n) return;
    float4 v = *reinterpret_cast<const float4*>(x + i);
    __nv_bfloat16 h0 = __float2bfloat16(v.x);
    __nv_bfloat16 h1 = __float2bfloat16(v.y);
    __nv_bfloat16 h2 = __float2bfloat16(v.z);
    __nv_bfloat16 h3 = __float2bfloat16(v.w);
    __nv_bfloat16 l0 = __float2bfloat16(v.x - __bfloat162float(h0));
    __nv_bfloat16 l1 = __float2bfloat16(v.y - __bfloat162float(h1));
    __nv_bfloat16 l2 = __float2bfloat16(v.z - __bfloat162float(h2));
    __nv_bfloat16 l3 = __float2bfloat16(v.w - __bfloat162float(h3));
    __nv_bfloat162* hp = reinterpret_cast<__nv_bfloat162*>(hi + i);
    __nv_bfloat162* lp = reinterpret_cast<__nv_bfloat162*>(lo + i);
    hp[0] = __halves2bfloat162(h0, h1);
    hp[1] = __halves2bfloat162(h2, h3);
    lp[0] = __halves2bfloat162(l0, l1);
    lp[1] = __halves2bfloat162(l2, l3);
}

// ============================================================================
// helpers
// ============================================================================
__device__ __forceinline__ void cp16(uint32_t dst, const void* src)
{
    asm volatile("cp.async.cg.shared.global [%0], [%1], 16;\n" :: "r"(dst), "l"(src));
}
__device__ __forceinline__ void cp_commit()
{
    asm volatile("cp.async.commit_group;\n" ::: "memory");
}
__device__ __forceinline__ void cp_wait0()
{
    asm volatile("cp.async.wait_group 0;\n" ::: "memory");
}
__device__ __forceinline__ void ldsm4(uint32_t* r, uint32_t addr)
{
    asm volatile("ldmatrix.sync.aligned.m8n8.x4.shared.b16 {%0,%1,%2,%3}, [%4];\n"
                 : "=r"(r[0]), "=r"(r[1]), "=r"(r[2]), "=r"(r[3]) : "r"(addr));
}
__device__ __forceinline__ void mma16816(float* c, const uint32_t* a, uint32_t b0, uint32_t b1)
{
    asm volatile("mma.sync.aligned.m16n8k16.row.col.f32.bf16.bf16.f32 "
                 "{%0,%1,%2,%3},{%4,%5,%6,%7},{%8,%9},{%0,%1,%2,%3};\n"
                 : "+f"(c[0]), "+f"(c[1]), "+f"(c[2]), "+f"(c[3])
                 : "r"(a[0]), "r"(a[1]), "r"(a[2]), "r"(a[3]), "r"(b0), "r"(b1));
}
__device__ __forceinline__ uint32_t pack_bf2(float a, float b)
{
    __nv_bfloat162 p = __floats2bfloat162_rn(a, b);
    return *reinterpret_cast<uint32_t*>(&p);
}
__device__ __forceinline__ void split1(float v, __nv_bfloat16& h, __nv_bfloat16& l)
{
    h = __float2bfloat16(v);
    l = __float2bfloat16(v - __bfloat162float(h));
}
// split two floats into packed hi pair + lo pair
__device__ __forceinline__ void split2_pack(float a, float b, uint32_t& hi, uint32_t& lo)
{
    __nv_bfloat16 ha, hb, la, lb;
    split1(a, ha, la);
    split1(b, hb, lb);
    __nv_bfloat162 hp = __halves2bfloat162(ha, hb);
    __nv_bfloat162 lp = __halves2bfloat162(la, lb);
    hi = *reinterpret_cast<uint32_t*>(&hp);
    lo = *reinterpret_cast<uint32_t*>(&lp);
}
__device__ __forceinline__ float fast_exp(float x)
{
    x = fmaxf(x, -87.0f);
    float y  = x * 1.4426950408889634f;
    float nf = y + 12582912.0f;
    float n  = nf - 12582912.0f;
    float f  = y - n;
    float p  = 1.3333558146e-3f;
    p = fmaf(p, f, 9.6181291076e-3f);
    p = fmaf(p, f, 5.5504108664e-2f);
    p = fmaf(p, f, 2.4022650696e-1f);
    p = fmaf(p, f, 6.9314718056e-1f);
    p = fmaf(p, f, 1.0f);
    int i = __float_as_int(nf) - 0x4B400000;
    float s = __int_as_float((i + 127) << 23);
    return p * s;
}

// ============================================================================
// GEMM: Y = X[M,K] @ W[N,K]^T via bf16 hi/lo split MMA.
// ============================================================================
#define GBM 128
#define GBN 64
#define GBK 32
#define GPADS 40

#define OFF_AHI 0
#define OFF_ALO (GBM*GPADS)
#define OFF_BHI (2*GBM*GPADS)
#define OFF_BLO (2*GBM*GPADS + GBN*GPADS)
#define STAGE_ELEMS (2*GBM*GPADS + 2*GBN*GPADS)
#define GEMM_SMEM_BYTES (STAGE_ELEMS * 2 * 2)

__device__ __forceinline__ void gemm_load_stage(uint32_t sbase, int t, int m0, int n0,
                                                int k0, int K,
                                                const __nv_bfloat16* Ahi,
                                                const __nv_bfloat16* Alo,
                                                const __nv_bfloat16* Bhi,
                                                const __nv_bfloat16* Blo)
{
    int r0 = t >> 2;
    int c0 = (t & 3) * 8;
    size_t ga0 = (size_t)(m0 + r0) * K + k0 + c0;
    uint32_t sa0 = (uint32_t)((r0 * GPADS + c0) * 2);
    cp16(sbase + OFF_AHI * 2 + sa0, Ahi + ga0);
    cp16(sbase + OFF_ALO * 2 + sa0, Alo + ga0);
    size_t ga1 = (size_t)(m0 + 64 + r0) * K + k0 + c0;
    uint32_t sa1 = (uint32_t)(((64 + r0) * GPADS + c0) * 2);
    cp16(sbase + OFF_AHI * 2 + sa1, Ahi + ga1);
    cp16(sbase + OFF_ALO * 2 + sa1, Alo + ga1);
    int rb = r0 & 63;
    size_t gb = (size_t)(n0 + rb) * K + k0 + c0;
    uint32_t sb = (uint32_t)((rb * GPADS + c0) * 2);
    cp16(sbase + OFF_BHI * 2 + sb, Bhi + gb);
    cp16(sbase + OFF_BLO * 2 + sb, Blo + gb);
}

__global__ void __launch_bounds__(256)
gemm_nt_bf16s_kernel(const __nv_bfloat16* __restrict__ Ahi,
                     const __nv_bfloat16* __restrict__ Alo,
                     const __nv_bfloat16* __restrict__ Bhi,
                     const __nv_bfloat16* __restrict__ Blo,
                     float* __restrict__ Yf,
                     __nv_bfloat16* __restrict__ Yhi,
                     __nv_bfloat16* __restrict__ Ylo,
                     float scale,
                     int M, int N, int K)
{
    extern __shared__ __nv_bfloat16 smem[];
    const uint32_t smem_base = (uint32_t)__cvta_generic_to_shared(smem);

    const int t    = threadIdx.x;
    const int lane = t & 31;
    const int wid  = t >> 5;
    const int wm   = wid & 3;
    const int wn   = wid >> 2;
    const int m0   = blockIdx.y * GBM;
    const int n0   = blockIdx.x * GBN;

    float acc[2][4][4];
    #pragma unroll
    for (int i = 0; i < 2; i++)
        #pragma unroll
        for (int j = 0; j < 4; j++)
            #pragma unroll
            for (int l = 0; l < 4; l++)
                acc[i][j][l] = 0.0f;

    gemm_load_stage(smem_base, t, m0, n0, 0, K, Ahi, Alo, Bhi, Blo);
    cp_commit();

    const int NIT = K / GBK;
    for (int it = 0; it < NIT; it++) {
        cp_wait0();
        __syncthreads();
        int cur = it & 1;
        if (it + 1 < NIT) {
            gemm_load_stage(smem_base + (uint32_t)((cur ^ 1) * STAGE_ELEMS * 2),
                            t, m0, n0, (it + 1) * GBK, K, Ahi, Alo, Bhi, Blo);
            cp_commit();
        }

        uint32_t sbase = smem_base + (uint32_t)(cur * STAGE_ELEMS * 2);

        #pragma unroll
        for (int ksub = 0; ksub < 2; ksub++) {
            uint32_t ahi[2][4];
            uint32_t alo[2][4];
            #pragma unroll
            for (int mt = 0; mt < 2; mt++) {
                int row = wm * 32 + mt * 16 + (lane & 15);
                uint32_t koff = (uint32_t)(((lane >> 4) * 16) + ksub * 32);
                ldsm4(ahi[mt], sbase + (uint32_t)((OFF_AHI + row * GPADS) * 2) + koff);
                ldsm4(alo[mt], sbase + (uint32_t)((OFF_ALO + row * GPADS) * 2) + koff);
            }
            uint32_t bhi[2][4];
            uint32_t blo[2][4];
            #pragma unroll
            for (int np = 0; np < 2; np++) {
                int row = wn * 32 + np * 16 + (((lane >> 4) << 3) | (lane & 7));
                uint32_t koff = (uint32_t)((((lane >> 3) & 1) * 16) + ksub * 32);
                ldsm4(bhi[np], sbase + (uint32_t)((OFF_BHI + row * GPADS) * 2) + koff);
                ldsm4(blo[np], sbase + (uint32_t)((OFF_BLO + row * GPADS) * 2) + koff);
            }
            #pragma unroll
            for (int mt = 0; mt < 2; mt++) {
                #pragma unroll
                for (int nt = 0; nt < 4; nt++) {
                    int np = nt >> 1;
                    int h  = (nt & 1) * 2;
                    mma16816(acc[mt][nt], ahi[mt], bhi[np][h], bhi[np][h + 1]);
                    mma16816(acc[mt][nt], ahi[mt], blo[np][h], blo[np][h + 1]);
                    mma16816(acc[mt][nt], alo[mt], bhi[np][h], bhi[np][h + 1]);
                }
            }
        }
        __syncthreads();
    }

    #pragma unroll
    for (int mt = 0; mt < 2; mt++) {
        #pragma unroll
        for (int nt = 0; nt < 4; nt++) {
            int row = m0 + wm * 32 + mt * 16 + (lane >> 2);
            int col = n0 + wn * 32 + nt * 8 + (lane & 3) * 2;
            float v0 = acc[mt][nt][0] * scale;
            float v1 = acc[mt][nt][1] * scale;
            float v2 = acc[mt][nt][2] * scale;
            float v3 = acc[mt][nt][3] * scale;
            if (Yf) {
                Yf[(size_t)row * N + col]           = v0;
                Yf[(size_t)row * N + col + 1]       = v1;
                Yf[(size_t)(row + 8) * N + col]     = v2;
                Yf[(size_t)(row + 8) * N + col + 1] = v3;
            }
            if (Yhi) {
                __nv_bfloat16 h0, h1, h2, h3, l0, l1, l2, l3;
                split1(v0, h0, l0);
                split1(v1, h1, l1);
                split1(v2, h2, l2);
                split1(v3, h3, l3);
                *reinterpret_cast<__nv_bfloat162*>(Yhi + (size_t)row * N + col) =
                    __halves2bfloat162(h0, h1);
                *reinterpret_cast<__nv_bfloat162*>(Ylo + (size_t)row * N + col) =
                    __halves2bfloat162(l0, l1);
                *reinterpret_cast<__nv_bfloat162*>(Yhi + (size_t)(row + 8) * N + col) =
                    __halves2bfloat162(h2, h3);
                *reinterpret_cast<__nv_bfloat162*>(Ylo + (size_t)(row + 8) * N + col) =
                    __halves2bfloat162(l2, l3);
            }
        }
    }
}

// ============================================================================
// Tensor-core flash attention; P now hi/lo split for PV (3-MMA scheme).
// ============================================================================
#define APAD 72
#define S_QHI 0
#define S_QLO (64*APAD)
#define S_KHI (2*64*APAD)
#define S_KLO (3*64*APAD)
#define S_VHI (4*64*APAD)
#define S_VLO (5*64*APAD)
#define S_BIAS_ELEM (6*64*APAD)
#define ATTN2_SMEM_BYTES (S_BIAS_ELEM*2 + 64*4)

__global__ void __launch_bounds__(128)
attn_mma_kernel(const __nv_bfloat16* __restrict__ Qh, const __nv_bfloat16* __restrict__ Ql,
                const __nv_bfloat16* __restrict__ Kh, const __nv_bfloat16* __restrict__ Kl,
                const __nv_bfloat16* __restrict__ Vh, const __nv_bfloat16* __restrict__ Vl,
                const float* __restrict__ bias,
                __nv_bfloat16* __restrict__ Oh, __nv_bfloat16* __restrict__ Ol)
{
    extern __shared__ __nv_bfloat16 sm2[];
    const uint32_t sbase = (uint32_t)__cvta_generic_to_shared(sm2);
    float* sB = reinterpret_cast<float*>(sm2 + S_BIAS_ELEM);

    const int t    = threadIdx.x;
    const int lane = t & 31;
    const int w    = t >> 5;
    const int qb   = blockIdx.x;
    const int h    = blockIdx.y;
    const int b    = blockIdx.z;

    const size_t qrow0  = (size_t)b * SQ + (size_t)qb * 64;
    const size_t kvbase = (size_t)b * SKV;
    const int hcol = h * HD;

    #pragma unroll
    for (int i = 0; i < 4; i++) {
        int ch = t + i * 128;
        int r  = ch >> 3;
        int c  = (ch & 7) * 8;
        size_t g = (qrow0 + r) * EMBED + hcol + c;
        uint32_t so = (uint32_t)((r * APAD + c) * 2);
        cp16(sbase + S_QHI * 2 + so, Qh + g);
        cp16(sbase + S_QLO * 2 + so, Ql + g);
    }
    cp_commit();

    float s[8][4];
    float o[8][4];
    #pragma unroll
    for (int i = 0; i < 8; i++)
        #pragma unroll
        for (int j = 0; j < 4; j++)
            o[i][j] = 0.0f;
    float m0 = -INFINITY, m1 = -INFINITY;
    float l0 = 0.0f, l1 = 0.0f;

    cp_wait0();
    __syncthreads();

    for (int kt = 0; kt < SKV / 64; kt++) {
        __syncthreads();
        #pragma unroll
        for (int i = 0; i < 4; i++) {
            int ch = t + i * 128;
            int r  = ch >> 3;
            int c  = (ch & 7) * 8;
            size_t g = (kvbase + kt * 64 + r) * EMBED + hcol + c;
            uint32_t so = (uint32_t)((r * APAD + c) * 2);
            cp16(sbase + S_KHI * 2 + so, Kh + g);
            cp16(sbase + S_KLO * 2 + so, Kl + g);
        }
        cp_commit();
        #pragma unroll
        for (int i = 0; i < 4; i++) {
            int ch = t + i * 128;
            int r  = ch >> 3;
            int c  = (ch & 7) * 8;
            size_t g = (kvbase + kt * 64 + r) * EMBED + hcol + c;
            uint4 hv = *reinterpret_cast<const uint4*>(Vh + g);
            uint4 lv = *reinterpret_cast<const uint4*>(Vl + g);
            const __nv_bfloat16* hp = reinterpret_cast<const __nv_bfloat16*>(&hv);
            const __nv_bfloat16* lp = reinterpret_cast<const __nv_bfloat16*>(&lv);
            #pragma unroll
            for (int j = 0; j < 8; j++) {
                sm2[S_VHI + (c + j) * APAD + r] = hp[j];
                sm2[S_VLO + (c + j) * APAD + r] = lp[j];
            }
        }
        if (t < 64) {
            sB[t] = bias[kvbase + kt * 64 + t];
        }
        cp_wait0();
        __syncthreads();

        // ---- S = Q K^T ----
        #pragma unroll
        for (int i = 0; i < 8; i++)
            #pragma unroll
            for (int j = 0; j < 4; j++)
                s[i][j] = 0.0f;

        #pragma unroll
        for (int ks = 0; ks < 4; ks++) {
            uint32_t ahi[4];
            uint32_t alo[4];
            {
                int row = w * 16 + (lane & 15);
                uint32_t koff = (uint32_t)(((lane >> 4) * 16) + ks * 32);
                ldsm4(ahi, sbase + (uint32_t)((S_QHI + row * APAD) * 2) + koff);
                ldsm4(alo, sbase + (uint32_t)((S_QLO + row * APAD) * 2) + koff);
            }
            uint32_t khi[4][4];
            uint32_t klo[4][4];
            #pragma unroll
            for (int g = 0; g < 4; g++) {
                int row = g * 16 + (((lane >> 4) << 3) | (lane & 7));
                uint32_t koff = (uint32_t)((((lane >> 3) & 1) * 16) + ks * 32);
                ldsm4(khi[g], sbase + (uint32_t)((S_KHI + row * APAD) * 2) + koff);
                ldsm4(klo[g], sbase + (uint32_t)((S_KLO + row * APAD) * 2) + koff);
            }
            #pragma unroll
            for (int nt = 0; nt < 8; nt++) {
                int g  = nt >> 1;
                int hh = (nt & 1) * 2;
                mma16816(s[nt], ahi, khi[g][hh], khi[g][hh + 1]);
                mma16816(s[nt], ahi, klo[g][hh], klo[g][hh + 1]);
                mma16816(s[nt], alo, khi[g][hh], khi[g][hh + 1]);
            }
        }

        // bias
        #pragma unroll
        for (int nt = 0; nt < 8; nt++) {
            int c0 = nt * 8 + (lane & 3) * 2;
            float b0 = sB[c0];
            float b1 = sB[c0 + 1];
            s[nt][0] += b0;
            s[nt][1] += b1;
            s[nt][2] += b0;
            s[nt][3] += b1;
        }

        // ---- online softmax ----
        {
            float mx = fmaxf(s[0][0], s[0][1]);
            #pragma unroll
            for (int nt = 1; nt < 8; nt++)
                mx = fmaxf(mx, fmaxf(s[nt][0], s[nt][1]));
            mx = fmaxf(mx, __shfl_xor_sync(0xffffffffu, mx, 1));
            mx = fmaxf(mx, __shfl_xor_sync(0xffffffffu, mx, 2));
            float mn = fmaxf(m0, mx);
            float corr = fast_exp(m0 - mn);
            m0 = mn;
            float sum = 0.0f;
            #pragma unroll
            for (int nt = 0; nt < 8; nt++) {
                s[nt][0] = fast_exp(s[nt][0] - mn);
                s[nt][1] = fast_exp(s[nt][1] - mn);
                sum += s[nt][0] + s[nt][1];
            }
            sum += __shfl_xor_sync(0xffffffffu, sum, 1);
            sum += __shfl_xor_sync(0xffffffffu, sum, 2);
            l0 = l0 * corr + sum;
            #pragma unroll
            for (int nt = 0; nt < 8; nt++) {
                o[nt][0] *= corr;
                o[nt][1] *= corr;
            }
        }
        {
            float mx = fmaxf(s[0][2], s[0][3]);
            #pragma unroll
            for (int nt = 1; nt < 8; nt++)
                mx = fmaxf(mx, fmaxf(s[nt][2], s[nt][3]));
            mx = fmaxf(mx, __shfl_xor_sync(0xffffffffu, mx, 1));
            mx = fmaxf(mx, __shfl_xor_sync(0xffffffffu, mx, 2));
            float mn = fmaxf(m1, mx);
            float corr = fast_exp(m1 - mn);
            m1 = mn;
            float sum = 0.0f;
            #pragma unroll
            for (int nt = 0; nt < 8; nt++) {
                s[nt][2] = fast_exp(s[nt][2] - mn);
                s[nt][3] = fast_exp(s[nt][3] - mn);
                sum += s[nt][2] + s[nt][3];
            }
            sum += __shfl_xor_sync(0xffffffffu, sum, 1);
            sum += __shfl_xor_sync(0xffffffffu, sum, 2);
            l1 = l1 * corr + sum;
            #pragma unroll
            for (int nt = 0; nt < 8; nt++) {
                o[nt][2] *= corr;
                o[nt][3] *= corr;
            }
        }

        // ---- O += P V  (P hi/lo split: 3-MMA scheme) ----
        #pragma unroll
        for (int u = 0; u < 4; u++) {
            uint32_t ph[4];
            uint32_t pl[4];
            split2_pack(s[2 * u][0],     s[2 * u][1],     ph[0], pl[0]);
            split2_pack(s[2 * u][2],     s[2 * u][3],     ph[1], pl[1]);
            split2_pack(s[2 * u + 1][0], s[2 * u + 1][1], ph[2], pl[2]);
            split2_pack(s[2 * u + 1][2], s[2 * u + 1][3], ph[3], pl[3]);
            uint32_t vhi[4][4];
            uint32_t vlo[4][4];
            #pragma unroll
            for (int g = 0; g < 4; g++) {
                int row = g * 16 + (((lane >> 4) << 3) | (lane & 7));
                uint32_t koff = (uint32_t)((((lane >> 3) & 1) * 16) + u * 32);
                ldsm4(vhi[g], sbase + (uint32_t)((S_VHI + row * APAD) * 2) + koff);
                ldsm4(vlo[g], sbase + (uint32_t)((S_VLO + row * APAD) * 2) + koff);
            }
            #pragma unroll
            for (int nt = 0; nt < 8; nt++) {
                int g  = nt >> 1;
                int hh = (nt & 1) * 2;
                mma16816(o[nt], ph, vhi[g][hh], vhi[g][hh + 1]);
                mma16816(o[nt], ph, vlo[g][hh], vlo[g][hh + 1]);
                mma16816(o[nt], pl, vhi[g][hh], vhi[g][hh + 1]);
            }
        }
    }

    // ---- epilogue ----
    {
        float inv0 = 1.0f / l0;
        float inv1 = 1.0f / l1;
        int r = lane >> 2;
        size_t row0 = (qrow0 + w * 16 + r) * EMBED;
        size_t row1 = row0 + 8 * EMBED;
        #pragma unroll
        for (int nt = 0; nt < 8; nt++) {
            int col = hcol + nt * 8 + (lane & 3) * 2;
            float v0 = o[nt][0] * inv0;
            float v1 = o[nt][1] * inv0;
            float v2 = o[nt][2] * inv1;
            float v3 = o[nt][3] * inv1;
            __nv_bfloat16 h0, h1, h2, h3, e0, e1, e2, e3;
            split1(v0, h0, e0);
            split1(v1, h1, e1);
            split1(v2, h2, e2);
            split1(v3, h3, e3);
            *reinterpret_cast<__nv_bfloat162*>(Oh + row0 + col) = __halves2bfloat162(h0, h1);
            *reinterpret_cast<__nv_bfloat162*>(Ol + row0 + col) = __halves2bfloat162(e0, e1);
            *reinterpret_cast<__nv_bfloat162*>(Oh + row1 + col) = __halves2bfloat162(h2, h3);
            *reinterpret_cast<__nv_bfloat162*>(Ol + row1 + col) = __halves2bfloat162(e2, e3);
        }
    }
}

// ============================================================================
extern "C" void kernel_launch(void* const* d_in, const int* in_sizes, int n_in,
                              void* d_out, int out_size)
{
    const float* q    = (const float*)d_in[0];
    const float* k    = (const float*)d_in[1];
    const float* v    = (const float*)d_in[2];
    const float* bias = (const float*)d_in[3];
    const float* Wq   = (const float*)d_in[4];
    const float* Wk   = (const float*)d_in[5];
    const float* Wv   = (const float*)d_in[6];
    const float* Wo   = (const float*)d_in[7];
    float* out = (float*)d_out;

    __nv_bfloat16* xqh = 0; __nv_bfloat16* xql = 0;
    __nv_bfloat16* xkh = 0; __nv_bfloat16* xkl = 0;
    __nv_bfloat16* xvh = 0; __nv_bfloat16* xvl = 0;
    __nv_bfloat16* wqh = 0; __nv_bfloat16* wql = 0;
    __nv_bfloat16* wkh = 0; __nv_bfloat16* wkl = 0;
    __nv_bfloat16* wvh = 0; __nv_bfloat16* wvl = 0;
    __nv_bfloat16* woh = 0; __nv_bfloat16* wol = 0;
    __nv_bfloat16* pqh = 0; __nv_bfloat16* pql = 0;
    __nv_bfloat16* pkh = 0; __nv_bfloat16* pkl = 0;
    __nv_bfloat16* pvh = 0; __nv_bfloat16* pvl = 0;
    __nv_bfloat16* aoh = 0; __nv_bfloat16* aol = 0;
    cudaGetSymbolAddress((void**)&xqh, g_xq_hi);
    cudaGetSymbolAddress((void**)&xql, g_xq_lo);
    cudaGetSymbolAddress((void**)&xkh, g_xk_hi);
    cudaGetSymbolAddress((void**)&xkl, g_xk_lo);
    cudaGetSymbolAddress((void**)&xvh, g_xv_hi);
    cudaGetSymbolAddress((void**)&xvl, g_xv_lo);
    cudaGetSymbolAddress((void**)&wqh, g_wq_hi);
    cudaGetSymbolAddress((void**)&wql, g_wq_lo);
    cudaGetSymbolAddress((void**)&wkh, g_wk_hi);
    cudaGetSymbolAddress((void**)&wkl, g_wk_lo);
    cudaGetSymbolAddress((void**)&wvh, g_wv_hi);
    cudaGetSymbolAddress((void**)&wvl, g_wv_lo);
    cudaGetSymbolAddress((void**)&woh, g_wo_hi);
    cudaGetSymbolAddress((void**)&wol, g_wo_lo);
    cudaGetSymbolAddress((void**)&pqh, g_pq_hi);
    cudaGetSymbolAddress((void**)&pql, g_pq_lo);
    cudaGetSymbolAddress((void**)&pkh, g_pk_hi);
    cudaGetSymbolAddress((void**)&pkl, g_pk_lo);
    cudaGetSymbolAddress((void**)&pvh, g_pv_hi);
    cudaGetSymbolAddress((void**)&pvl, g_pv_lo);
    cudaGetSymbolAddress((void**)&aoh, g_ao_hi);
    cudaGetSymbolAddress((void**)&aol, g_ao_lo);

    cudaFuncSetAttribute(gemm_nt_bf16s_kernel, cudaFuncAttributeMaxDynamicSharedMemorySize,
                         GEMM_SMEM_BYTES);
    cudaFuncSetAttribute(attn_mma_kernel, cudaFuncAttributeMaxDynamicSharedMemorySize,
                         ATTN2_SMEM_BYTES);

    int actN = (int)NACT;
    int weiN = (int)NWEI;
    int actBlocks = actN / 4 / 256;
    int weiBlocks = weiN / 4 / 256;

    split_bf16_kernel<<<actBlocks, 256>>>(q, xqh, xql, actN);
    split_bf16_kernel<<<actBlocks, 256>>>(k, xkh, xkl, actN);
    split_bf16_kernel<<<actBlocks, 256>>>(v, xvh, xvl, actN);
    split_bf16_kernel<<<weiBlocks, 256>>>(Wq, wqh, wql, weiN);
    split_bf16_kernel<<<weiBlocks, 256>>>(Wk, wkh, wkl, weiN);
    split_bf16_kernel<<<weiBlocks, 256>>>(Wv, wvh, wvl, weiN);
    split_bf16_kernel<<<weiBlocks, 256>>>(Wo, woh, wol, weiN);

    dim3 gp(EMBED / GBN, MTOT / GBM);
    gemm_nt_bf16s_kernel<<<gp, 256, GEMM_SMEM_BYTES>>>(xqh, xql, wqh, wql,
                                                       (float*)0, pqh, pql, 0.125f,
                                                       MTOT, EMBED, EMBED);
    gemm_nt_bf16s_kernel<<<gp, 256, GEMM_SMEM_BYTES>>>(xkh, xkl, wkh, wkl,
                                                       (float*)0, pkh, pkl, 1.0f,
                                                       MTOT, EMBED, EMBED);
    gemm_nt_bf16s_kernel<<<gp, 256, GEMM_SMEM_BYTES>>>(xvh, xvl, wvh, wvl,
                                                       (float*)0, pvh, pvl, 1.0f,
                                                       MTOT, EMBED, EMBED);

    dim3 ga(SQ / 64, NHEAD, BATCH);
    attn_mma_kernel<<<ga, 128, ATTN2_SMEM_BYTES>>>(pqh, pql, pkh, pkl, pvh, pvl,
                                                   bias, aoh, aol);

    gemm_nt_bf16s_kernel<<<gp, 256, GEMM_SMEM_BYTES>>>(aoh, aol, woh, wol,
                                                       out, (__nv_bfloat16*)0,
                                                       (__nv_bfloat16*)0, 1.0f,
                                                       MTOT, EMBED, EMBED);
}

// round 7
// speedup vs baseline: 3.2681x; 1.2170x over previous
#include <cuda_runtime.h>
#include <cuda_bf16.h>
#include <math.h>
#include <stdint.h>

#define EMBED 1024
#define NHEAD 16
#define HD 64
#define BATCH 2
#define SQ 2048
#define SKV 2048
#define MTOT (BATCH*SQ)

#define NACT ((size_t)MTOT * EMBED)
#define NWEI ((size_t)EMBED * EMBED)

// ---- bf16 hi/lo split scratch ----
__device__ __align__(16) __nv_bfloat16 g_xq_hi[NACT];
__device__ __align__(16) __nv_bfloat16 g_xq_lo[NACT];
__device__ __align__(16) __nv_bfloat16 g_xk_hi[NACT];
__device__ __align__(16) __nv_bfloat16 g_xk_lo[NACT];
__device__ __align__(16) __nv_bfloat16 g_xv_hi[NACT];
__device__ __align__(16) __nv_bfloat16 g_xv_lo[NACT];
__device__ __align__(16) __nv_bfloat16 g_wq_hi[NWEI];
__device__ __align__(16) __nv_bfloat16 g_wq_lo[NWEI];
__device__ __align__(16) __nv_bfloat16 g_wk_hi[NWEI];
__device__ __align__(16) __nv_bfloat16 g_wk_lo[NWEI];
__device__ __align__(16) __nv_bfloat16 g_wv_hi[NWEI];
__device__ __align__(16) __nv_bfloat16 g_wv_lo[NWEI];
__device__ __align__(16) __nv_bfloat16 g_wo_hi[NWEI];
__device__ __align__(16) __nv_bfloat16 g_wo_lo[NWEI];
__device__ __align__(16) __nv_bfloat16 g_pq_hi[NACT];
__device__ __align__(16) __nv_bfloat16 g_pq_lo[NACT];
__device__ __align__(16) __nv_bfloat16 g_pk_hi[NACT];
__device__ __align__(16) __nv_bfloat16 g_pk_lo[NACT];
__device__ __align__(16) __nv_bfloat16 g_pv_hi[NACT];
__device__ __align__(16) __nv_bfloat16 g_pv_lo[NACT];
__device__ __align__(16) __nv_bfloat16 g_ao_hi[NACT];
__device__ __align__(16) __nv_bfloat16 g_ao_lo[NACT];

// ============================================================================
// fp32 -> bf16 hi/lo split
// ============================================================================
__global__ void split_bf16_kernel(const float* __restrict__ x,
                                  __nv_bfloat16* __restrict__ hi,
                                  __nv_bfloat16* __restrict__ lo,
                                  int n)
{
    int i = (blockIdx.x * blockDim.x + threadIdx.x) * 4;
    if (i >= n) return;
    float4 v = *reinterpret_cast<const float4*>(x + i);
    __nv_bfloat16 h0 = __float2bfloat16(v.x);
    __nv_bfloat16 h1 = __float2bfloat16(v.y);
    __nv_bfloat16 h2 = __float2bfloat16(v.z);
    __nv_bfloat16 h3 = __float2bfloat16(v.w);
    __nv_bfloat16 l0 = __float2bfloat16(v.x - __bfloat162float(h0));
    __nv_bfloat16 l1 = __float2bfloat16(v.y - __bfloat162float(h1));
    __nv_bfloat16 l2 = __float2bfloat16(v.z - __bfloat162float(h2));
    __nv_bfloat16 l3 = __float2bfloat16(v.w - __bfloat162float(h3));
    __nv_bfloat162* hp = reinterpret_cast<__nv_bfloat162*>(hi + i);
    __nv_bfloat162* lp = reinterpret_cast<__nv_bfloat162*>(lo + i);
    hp[0] = __halves2bfloat162(h0, h1);
    hp[1] = __halves2bfloat162(h2, h3);
    lp[0] = __halves2bfloat162(l0, l1);
    lp[1] = __halves2bfloat162(l2, l3);
}

// ============================================================================
// helpers
// ============================================================================
__device__ __forceinline__ void cp16(uint32_t dst, const void* src)
{
    asm volatile("cp.async.cg.shared.global [%0], [%1], 16;\n" :: "r"(dst), "l"(src));
}
__device__ __forceinline__ void cp_commit()
{
    asm volatile("cp.async.commit_group;\n" ::: "memory");
}
__device__ __forceinline__ void cp_wait0()
{
    asm volatile("cp.async.wait_group 0;\n" ::: "memory");
}
__device__ __forceinline__ void cp_wait1()
{
    asm volatile("cp.async.wait_group 1;\n" ::: "memory");
}
__device__ __forceinline__ void ldsm4(uint32_t* r, uint32_t addr)
{
    asm volatile("ldmatrix.sync.aligned.m8n8.x4.shared.b16 {%0,%1,%2,%3}, [%4];\n"
                 : "=r"(r[0]), "=r"(r[1]), "=r"(r[2]), "=r"(r[3]) : "r"(addr));
}
__device__ __forceinline__ void ldsm4t(uint32_t* r, uint32_t addr)
{
    asm volatile("ldmatrix.sync.aligned.m8n8.x4.trans.shared.b16 {%0,%1,%2,%3}, [%4];\n"
                 : "=r"(r[0]), "=r"(r[1]), "=r"(r[2]), "=r"(r[3]) : "r"(addr));
}
__device__ __forceinline__ void mma16816(float* c, const uint32_t* a, uint32_t b0, uint32_t b1)
{
    asm volatile("mma.sync.aligned.m16n8k16.row.col.f32.bf16.bf16.f32 "
                 "{%0,%1,%2,%3},{%4,%5,%6,%7},{%8,%9},{%0,%1,%2,%3};\n"
                 : "+f"(c[0]), "+f"(c[1]), "+f"(c[2]), "+f"(c[3])
                 : "r"(a[0]), "r"(a[1]), "r"(a[2]), "r"(a[3]), "r"(b0), "r"(b1));
}
__device__ __forceinline__ void split1(float v, __nv_bfloat16& h, __nv_bfloat16& l)
{
    h = __float2bfloat16(v);
    l = __float2bfloat16(v - __bfloat162float(h));
}
__device__ __forceinline__ void split2_pack(float a, float b, uint32_t& hi, uint32_t& lo)
{
    __nv_bfloat16 ha, hb, la, lb;
    split1(a, ha, la);
    split1(b, hb, lb);
    __nv_bfloat162 hp = __halves2bfloat162(ha, hb);
    __nv_bfloat162 lp = __halves2bfloat162(la, lb);
    hi = *reinterpret_cast<uint32_t*>(&hp);
    lo = *reinterpret_cast<uint32_t*>(&lp);
}
__device__ __forceinline__ float fast_exp(float x)
{
    x = fmaxf(x, -87.0f);
    float y  = x * 1.4426950408889634f;
    float nf = y + 12582912.0f;
    float n  = nf - 12582912.0f;
    float f  = y - n;
    float p  = 1.3333558146e-3f;
    p = fmaf(p, f, 9.6181291076e-3f);
    p = fmaf(p, f, 5.5504108664e-2f);
    p = fmaf(p, f, 2.4022650696e-1f);
    p = fmaf(p, f, 6.9314718056e-1f);
    p = fmaf(p, f, 1.0f);
    int i = __float_as_int(nf) - 0x4B400000;
    float s = __int_as_float((i + 127) << 23);
    return p * s;
}

// ============================================================================
// GEMM: Y = X[M,K] @ W[N,K]^T via bf16 hi/lo split MMA. 3-stage cp.async ring.
// ============================================================================
#define GBM 128
#define GBN 64
#define GBK 32
#define GPADS 40
#define GSTAGES 3

#define OFF_AHI 0
#define OFF_ALO (GBM*GPADS)
#define OFF_BHI (2*GBM*GPADS)
#define OFF_BLO (2*GBM*GPADS + GBN*GPADS)
#define STAGE_ELEMS (2*GBM*GPADS + 2*GBN*GPADS)
#define GEMM_SMEM_BYTES (STAGE_ELEMS * 2 * GSTAGES)

__device__ __forceinline__ void gemm_load_stage(uint32_t sbase, int t, int m0, int n0,
                                                int k0, int K,
                                                const __nv_bfloat16* Ahi,
                                                const __nv_bfloat16* Alo,
                                                const __nv_bfloat16* Bhi,
                                                const __nv_bfloat16* Blo)
{
    int r0 = t >> 2;
    int c0 = (t & 3) * 8;
    size_t ga0 = (size_t)(m0 + r0) * K + k0 + c0;
    uint32_t sa0 = (uint32_t)((r0 * GPADS + c0) * 2);
    cp16(sbase + OFF_AHI * 2 + sa0, Ahi + ga0);
    cp16(sbase + OFF_ALO * 2 + sa0, Alo + ga0);
    size_t ga1 = (size_t)(m0 + 64 + r0) * K + k0 + c0;
    uint32_t sa1 = (uint32_t)(((64 + r0) * GPADS + c0) * 2);
    cp16(sbase + OFF_AHI * 2 + sa1, Ahi + ga1);
    cp16(sbase + OFF_ALO * 2 + sa1, Alo + ga1);
    int rb = r0 & 63;
    size_t gb = (size_t)(n0 + rb) * K + k0 + c0;
    uint32_t sb = (uint32_t)((rb * GPADS + c0) * 2);
    cp16(sbase + OFF_BHI * 2 + sb, Bhi + gb);
    cp16(sbase + OFF_BLO * 2 + sb, Blo + gb);
}

__global__ void __launch_bounds__(256)
gemm_nt_bf16s_kernel(const __nv_bfloat16* __restrict__ Ahi,
                     const __nv_bfloat16* __restrict__ Alo,
                     const __nv_bfloat16* __restrict__ Bhi,
                     const __nv_bfloat16* __restrict__ Blo,
                     float* __restrict__ Yf,
                     __nv_bfloat16* __restrict__ Yhi,
                     __nv_bfloat16* __restrict__ Ylo,
                     float scale,
                     int M, int N, int K)
{
    extern __shared__ __nv_bfloat16 smem[];
    const uint32_t smem_base = (uint32_t)__cvta_generic_to_shared(smem);

    const int t    = threadIdx.x;
    const int lane = t & 31;
    const int wid  = t >> 5;
    const int wm   = wid & 3;
    const int wn   = wid >> 2;
    const int m0   = blockIdx.y * GBM;
    const int n0   = blockIdx.x * GBN;

    float acc[2][4][4];
    #pragma unroll
    for (int i = 0; i < 2; i++)
        #pragma unroll
        for (int j = 0; j < 4; j++)
            #pragma unroll
            for (int l = 0; l < 4; l++)
                acc[i][j][l] = 0.0f;

    const int NIT = K / GBK;
    // preload 2 stages
    gemm_load_stage(smem_base, t, m0, n0, 0, K, Ahi, Alo, Bhi, Blo);
    cp_commit();
    gemm_load_stage(smem_base + (uint32_t)(STAGE_ELEMS * 2), t, m0, n0, GBK, K,
                    Ahi, Alo, Bhi, Blo);
    cp_commit();

    int stage = 0;
    for (int it = 0; it < NIT; it++) {
        if (it < NIT - 1) {
            cp_wait1();
        } else {
            cp_wait0();
        }
        __syncthreads();
        if (it + 2 < NIT) {
            int ls = stage + 2;
            if (ls >= GSTAGES) ls -= GSTAGES;
            gemm_load_stage(smem_base + (uint32_t)(ls * STAGE_ELEMS * 2),
                            t, m0, n0, (it + 2) * GBK, K, Ahi, Alo, Bhi, Blo);
            cp_commit();
        }

        uint32_t sbase = smem_base + (uint32_t)(stage * STAGE_ELEMS * 2);

        #pragma unroll
        for (int ksub = 0; ksub < 2; ksub++) {
            uint32_t ahi[2][4];
            uint32_t alo[2][4];
            #pragma unroll
            for (int mt = 0; mt < 2; mt++) {
                int row = wm * 32 + mt * 16 + (lane & 15);
                uint32_t koff = (uint32_t)(((lane >> 4) * 16) + ksub * 32);
                ldsm4(ahi[mt], sbase + (uint32_t)((OFF_AHI + row * GPADS) * 2) + koff);
                ldsm4(alo[mt], sbase + (uint32_t)((OFF_ALO + row * GPADS) * 2) + koff);
            }
            uint32_t bhi[2][4];
            uint32_t blo[2][4];
            #pragma unroll
            for (int np = 0; np < 2; np++) {
                int row = wn * 32 + np * 16 + (((lane >> 4) << 3) | (lane & 7));
                uint32_t koff = (uint32_t)((((lane >> 3) & 1) * 16) + ksub * 32);
                ldsm4(bhi[np], sbase + (uint32_t)((OFF_BHI + row * GPADS) * 2) + koff);
                ldsm4(blo[np], sbase + (uint32_t)((OFF_BLO + row * GPADS) * 2) + koff);
            }
            #pragma unroll
            for (int mt = 0; mt < 2; mt++) {
                #pragma unroll
                for (int nt = 0; nt < 4; nt++) {
                    int np = nt >> 1;
                    int h  = (nt & 1) * 2;
                    mma16816(acc[mt][nt], ahi[mt], bhi[np][h], bhi[np][h + 1]);
                    mma16816(acc[mt][nt], ahi[mt], blo[np][h], blo[np][h + 1]);
                    mma16816(acc[mt][nt], alo[mt], bhi[np][h], bhi[np][h + 1]);
                }
            }
        }
        __syncthreads();
        stage++;
        if (stage >= GSTAGES) stage -= GSTAGES;
    }

    #pragma unroll
    for (int mt = 0; mt < 2; mt++) {
        #pragma unroll
        for (int nt = 0; nt < 4; nt++) {
            int row = m0 + wm * 32 + mt * 16 + (lane >> 2);
            int col = n0 + wn * 32 + nt * 8 + (lane & 3) * 2;
            float v0 = acc[mt][nt][0] * scale;
            float v1 = acc[mt][nt][1] * scale;
            float v2 = acc[mt][nt][2] * scale;
            float v3 = acc[mt][nt][3] * scale;
            if (Yf) {
                Yf[(size_t)row * N + col]           = v0;
                Yf[(size_t)row * N + col + 1]       = v1;
                Yf[(size_t)(row + 8) * N + col]     = v2;
                Yf[(size_t)(row + 8) * N + col + 1] = v3;
            }
            if (Yhi) {
                __nv_bfloat16 h0, h1, h2, h3, l0, l1, l2, l3;
                split1(v0, h0, l0);
                split1(v1, h1, l1);
                split1(v2, h2, l2);
                split1(v3, h3, l3);
                *reinterpret_cast<__nv_bfloat162*>(Yhi + (size_t)row * N + col) =
                    __halves2bfloat162(h0, h1);
                *reinterpret_cast<__nv_bfloat162*>(Ylo + (size_t)row * N + col) =
                    __halves2bfloat162(l0, l1);
                *reinterpret_cast<__nv_bfloat162*>(Yhi + (size_t)(row + 8) * N + col) =
                    __halves2bfloat162(h2, h3);
                *reinterpret_cast<__nv_bfloat162*>(Ylo + (size_t)(row + 8) * N + col) =
                    __halves2bfloat162(l2, l3);
            }
        }
    }
}

// ============================================================================
// Tensor-core flash attention. V stored [kv][d] like K; V fragments via
// ldmatrix.trans (no manual transpose, no conflicted STS).
// ============================================================================
#define APAD 72
#define S_QHI 0
#define S_QLO (64*APAD)
#define S_KHI (2*64*APAD)
#define S_KLO (3*64*APAD)
#define S_VHI (4*64*APAD)
#define S_VLO (5*64*APAD)
#define S_BIAS_ELEM (6*64*APAD)
#define ATTN2_SMEM_BYTES (S_BIAS_ELEM*2 + 64*4)

__global__ void __launch_bounds__(128)
attn_mma_kernel(const __nv_bfloat16* __restrict__ Qh, const __nv_bfloat16* __restrict__ Ql,
                const __nv_bfloat16* __restrict__ Kh, const __nv_bfloat16* __restrict__ Kl,
                const __nv_bfloat16* __restrict__ Vh, const __nv_bfloat16* __restrict__ Vl,
                const float* __restrict__ bias,
                __nv_bfloat16* __restrict__ Oh, __nv_bfloat16* __restrict__ Ol)
{
    extern __shared__ __nv_bfloat16 sm2[];
    const uint32_t sbase = (uint32_t)__cvta_generic_to_shared(sm2);
    float* sB = reinterpret_cast<float*>(sm2 + S_BIAS_ELEM);

    const int t    = threadIdx.x;
    const int lane = t & 31;
    const int w    = t >> 5;
    const int qb   = blockIdx.x;
    const int h    = blockIdx.y;
    const int b    = blockIdx.z;

    const size_t qrow0  = (size_t)b * SQ + (size_t)qb * 64;
    const size_t kvbase = (size_t)b * SKV;
    const int hcol = h * HD;

    #pragma unroll
    for (int i = 0; i < 4; i++) {
        int ch = t + i * 128;
        int r  = ch >> 3;
        int c  = (ch & 7) * 8;
        size_t g = (qrow0 + r) * EMBED + hcol + c;
        uint32_t so = (uint32_t)((r * APAD + c) * 2);
        cp16(sbase + S_QHI * 2 + so, Qh + g);
        cp16(sbase + S_QLO * 2 + so, Ql + g);
    }
    cp_commit();

    float s[8][4];
    float o[8][4];
    #pragma unroll
    for (int i = 0; i < 8; i++)
        #pragma unroll
        for (int j = 0; j < 4; j++)
            o[i][j] = 0.0f;
    float m0 = -INFINITY, m1 = -INFINITY;
    float l0 = 0.0f, l1 = 0.0f;

    cp_wait0();
    __syncthreads();

    for (int kt = 0; kt < SKV / 64; kt++) {
        __syncthreads();
        // K and V tiles via cp.async, both [kv][d]
        #pragma unroll
        for (int i = 0; i < 4; i++) {
            int ch = t + i * 128;
            int r  = ch >> 3;
            int c  = (ch & 7) * 8;
            size_t g = (kvbase + kt * 64 + r) * EMBED + hcol + c;
            uint32_t so = (uint32_t)((r * APAD + c) * 2);
            cp16(sbase + S_KHI * 2 + so, Kh + g);
            cp16(sbase + S_KLO * 2 + so, Kl + g);
            cp16(sbase + S_VHI * 2 + so, Vh + g);
            cp16(sbase + S_VLO * 2 + so, Vl + g);
        }
        cp_commit();
        if (t < 64) {
            sB[t] = bias[kvbase + kt * 64 + t];
        }
        cp_wait0();
        __syncthreads();

        // ---- S = Q K^T ----
        #pragma unroll
        for (int i = 0; i < 8; i++)
            #pragma unroll
            for (int j = 0; j < 4; j++)
                s[i][j] = 0.0f;

        #pragma unroll
        for (int ks = 0; ks < 4; ks++) {
            uint32_t ahi[4];
            uint32_t alo[4];
            {
                int row = w * 16 + (lane & 15);
                uint32_t koff = (uint32_t)(((lane >> 4) * 16) + ks * 32);
                ldsm4(ahi, sbase + (uint32_t)((S_QHI + row * APAD) * 2) + koff);
                ldsm4(alo, sbase + (uint32_t)((S_QLO + row * APAD) * 2) + koff);
            }
            uint32_t khi[4][4];
            uint32_t klo[4][4];
            #pragma unroll
            for (int g = 0; g < 4; g++) {
                int row = g * 16 + (((lane >> 4) << 3) | (lane & 7));
                uint32_t koff = (uint32_t)((((lane >> 3) & 1) * 16) + ks * 32);
                ldsm4(khi[g], sbase + (uint32_t)((S_KHI + row * APAD) * 2) + koff);
                ldsm4(klo[g], sbase + (uint32_t)((S_KLO + row * APAD) * 2) + koff);
            }
            #pragma unroll
            for (int nt = 0; nt < 8; nt++) {
                int g  = nt >> 1;
                int hh = (nt & 1) * 2;
                mma16816(s[nt], ahi, khi[g][hh], khi[g][hh + 1]);
                mma16816(s[nt], ahi, klo[g][hh], klo[g][hh + 1]);
                mma16816(s[nt], alo, khi[g][hh], khi[g][hh + 1]);
            }
        }

        // bias
        #pragma unroll
        for (int nt = 0; nt < 8; nt++) {
            int c0 = nt * 8 + (lane & 3) * 2;
            float b0 = sB[c0];
            float b1 = sB[c0 + 1];
            s[nt][0] += b0;
            s[nt][1] += b1;
            s[nt][2] += b0;
            s[nt][3] += b1;
        }

        // ---- online softmax ----
        {
            float mx = fmaxf(s[0][0], s[0][1]);
            #pragma unroll
            for (int nt = 1; nt < 8; nt++)
                mx = fmaxf(mx, fmaxf(s[nt][0], s[nt][1]));
            mx = fmaxf(mx, __shfl_xor_sync(0xffffffffu, mx, 1));
            mx = fmaxf(mx, __shfl_xor_sync(0xffffffffu, mx, 2));
            float mn = fmaxf(m0, mx);
            float corr = fast_exp(m0 - mn);
            m0 = mn;
            float sum = 0.0f;
            #pragma unroll
            for (int nt = 0; nt < 8; nt++) {
                s[nt][0] = fast_exp(s[nt][0] - mn);
                s[nt][1] = fast_exp(s[nt][1] - mn);
                sum += s[nt][0] + s[nt][1];
            }
            sum += __shfl_xor_sync(0xffffffffu, sum, 1);
            sum += __shfl_xor_sync(0xffffffffu, sum, 2);
            l0 = l0 * corr + sum;
            #pragma unroll
            for (int nt = 0; nt < 8; nt++) {
                o[nt][0] *= corr;
                o[nt][1] *= corr;
            }
        }
        {
            float mx = fmaxf(s[0][2], s[0][3]);
            #pragma unroll
            for (int nt = 1; nt < 8; nt++)
                mx = fmaxf(mx, fmaxf(s[nt][2], s[nt][3]));
            mx = fmaxf(mx, __shfl_xor_sync(0xffffffffu, mx, 1));
            mx = fmaxf(mx, __shfl_xor_sync(0xffffffffu, mx, 2));
            float mn = fmaxf(m1, mx);
            float corr = fast_exp(m1 - mn);
            m1 = mn;
            float sum = 0.0f;
            #pragma unroll
            for (int nt = 0; nt < 8; nt++) {
                s[nt][2] = fast_exp(s[nt][2] - mn);
                s[nt][3] = fast_exp(s[nt][3] - mn);
                sum += s[nt][2] + s[nt][3];
            }
            sum += __shfl_xor_sync(0xffffffffu, sum, 1);
            sum += __shfl_xor_sync(0xffffffffu, sum, 2);
            l1 = l1 * corr + sum;
            #pragma unroll
            for (int nt = 0; nt < 8; nt++) {
                o[nt][2] *= corr;
                o[nt][3] *= corr;
            }
        }

        // ---- O += P V  (P hi/lo; V fragments via ldmatrix.trans) ----
        #pragma unroll
        for (int u = 0; u < 4; u++) {
            uint32_t ph[4];
            uint32_t pl[4];
            split2_pack(s[2 * u][0],     s[2 * u][1],     ph[0], pl[0]);
            split2_pack(s[2 * u][2],     s[2 * u][3],     ph[1], pl[1]);
            split2_pack(s[2 * u + 1][0], s[2 * u + 1][1], ph[2], pl[2]);
            split2_pack(s[2 * u + 1][2], s[2 * u + 1][3], ph[3], pl[3]);
            uint32_t vhi[4][4];
            uint32_t vlo[4][4];
            #pragma unroll
            for (int g = 0; g < 4; g++) {
                // trans load: addresses walk kv rows; fragments give V^T
                int kvrow = u * 16 + ((lane >> 3) & 1) * 8 + (lane & 7);
                int dcol  = g * 16 + ((lane >> 4) << 3);
                uint32_t a = sbase + (uint32_t)((kvrow * APAD + dcol) * 2);
                ldsm4t(vhi[g], a + (uint32_t)(S_VHI * 2));
                ldsm4t(vlo[g], a + (uint32_t)(S_VLO * 2));
            }
            #pragma unroll
            for (int nt = 0; nt < 8; nt++) {
                int g  = nt >> 1;
                int hh = (nt & 1) * 2;
                mma16816(o[nt], ph, vhi[g][hh], vhi[g][hh + 1]);
                mma16816(o[nt], ph, vlo[g][hh], vlo[g][hh + 1]);
                mma16816(o[nt], pl, vhi[g][hh], vhi[g][hh + 1]);
            }
        }
    }

    // ---- epilogue ----
    {
        float inv0 = 1.0f / l0;
        float inv1 = 1.0f / l1;
        int r = lane >> 2;
        size_t row0 = (qrow0 + w * 16 + r) * EMBED;
        size_t row1 = row0 + 8 * EMBED;
        #pragma unroll
        for (int nt = 0; nt < 8; nt++) {
            int col = hcol + nt * 8 + (lane & 3) * 2;
            float v0 = o[nt][0] * inv0;
            float v1 = o[nt][1] * inv0;
            float v2 = o[nt][2] * inv1;
            float v3 = o[nt][3] * inv1;
            __nv_bfloat16 h0, h1, h2, h3, e0, e1, e2, e3;
            split1(v0, h0, e0);
            split1(v1, h1, e1);
            split1(v2, h2, e2);
            split1(v3, h3, e3);
            *reinterpret_cast<__nv_bfloat162*>(Oh + row0 + col) = __halves2bfloat162(h0, h1);
            *reinterpret_cast<__nv_bfloat162*>(Ol + row0 + col) = __halves2bfloat162(e0, e1);
            *reinterpret_cast<__nv_bfloat162*>(Oh + row1 + col) = __halves2bfloat162(h2, h3);
            *reinterpret_cast<__nv_bfloat162*>(Ol + row1 + col) = __halves2bfloat162(e2, e3);
        }
    }
}

// ============================================================================
extern "C" void kernel_launch(void* const* d_in, const int* in_sizes, int n_in,
                              void* d_out, int out_size)
{
    const float* q    = (const float*)d_in[0];
    const float* k    = (const float*)d_in[1];
    const float* v    = (const float*)d_in[2];
    const float* bias = (const float*)d_in[3];
    const float* Wq   = (const float*)d_in[4];
    const float* Wk   = (const float*)d_in[5];
    const float* Wv   = (const float*)d_in[6];
    const float* Wo   = (const float*)d_in[7];
    float* out = (float*)d_out;

    __nv_bfloat16* xqh = 0; __nv_bfloat16* xql = 0;
    __nv_bfloat16* xkh = 0; __nv_bfloat16* xkl = 0;
    __nv_bfloat16* xvh = 0; __nv_bfloat16* xvl = 0;
    __nv_bfloat16* wqh = 0; __nv_bfloat16* wql = 0;
    __nv_bfloat16* wkh = 0; __nv_bfloat16* wkl = 0;
    __nv_bfloat16* wvh = 0; __nv_bfloat16* wvl = 0;
    __nv_bfloat16* woh = 0; __nv_bfloat16* wol = 0;
    __nv_bfloat16* pqh = 0; __nv_bfloat16* pql = 0;
    __nv_bfloat16* pkh = 0; __nv_bfloat16* pkl = 0;
    __nv_bfloat16* pvh = 0; __nv_bfloat16* pvl = 0;
    __nv_bfloat16* aoh = 0; __nv_bfloat16* aol = 0;
    cudaGetSymbolAddress((void**)&xqh, g_xq_hi);
    cudaGetSymbolAddress((void**)&xql, g_xq_lo);
    cudaGetSymbolAddress((void**)&xkh, g_xk_hi);
    cudaGetSymbolAddress((void**)&xkl, g_xk_lo);
    cudaGetSymbolAddress((void**)&xvh, g_xv_hi);
    cudaGetSymbolAddress((void**)&xvl, g_xv_lo);
    cudaGetSymbolAddress((void**)&wqh, g_wq_hi);
    cudaGetSymbolAddress((void**)&wql, g_wq_lo);
    cudaGetSymbolAddress((void**)&wkh, g_wk_hi);
    cudaGetSymbolAddress((void**)&wkl, g_wk_lo);
    cudaGetSymbolAddress((void**)&wvh, g_wv_hi);
    cudaGetSymbolAddress((void**)&wvl, g_wv_lo);
    cudaGetSymbolAddress((void**)&woh, g_wo_hi);
    cudaGetSymbolAddress((void**)&wol, g_wo_lo);
    cudaGetSymbolAddress((void**)&pqh, g_pq_hi);
    cudaGetSymbolAddress((void**)&pql, g_pq_lo);
    cudaGetSymbolAddress((void**)&pkh, g_pk_hi);
    cudaGetSymbolAddress((void**)&pkl, g_pk_lo);
    cudaGetSymbolAddress((void**)&pvh, g_pv_hi);
    cudaGetSymbolAddress((void**)&pvl, g_pv_lo);
    cudaGetSymbolAddress((void**)&aoh, g_ao_hi);
    cudaGetSymbolAddress((void**)&aol, g_ao_lo);

    cudaFuncSetAttribute(gemm_nt_bf16s_kernel, cudaFuncAttributeMaxDynamicSharedMemorySize,
                         GEMM_SMEM_BYTES);
    cudaFuncSetAttribute(attn_mma_kernel, cudaFuncAttributeMaxDynamicSharedMemorySize,
                         ATTN2_SMEM_BYTES);

    int actN = (int)NACT;
    int weiN = (int)NWEI;
    int actBlocks = actN / 4 / 256;
    int weiBlocks = weiN / 4 / 256;

    split_bf16_kernel<<<actBlocks, 256>>>(q, xqh, xql, actN);
    split_bf16_kernel<<<actBlocks, 256>>>(k, xkh, xkl, actN);
    split_bf16_kernel<<<actBlocks, 256>>>(v, xvh, xvl, actN);
    split_bf16_kernel<<<weiBlocks, 256>>>(Wq, wqh, wql, weiN);
    split_bf16_kernel<<<weiBlocks, 256>>>(Wk, wkh, wkl, weiN);
    split_bf16_kernel<<<weiBlocks, 256>>>(Wv, wvh, wvl, weiN);
    split_bf16_kernel<<<weiBlocks, 256>>>(Wo, woh, wol, weiN);

    dim3 gp(EMBED / GBN, MTOT / GBM);
    gemm_nt_bf16s_kernel<<<gp, 256, GEMM_SMEM_BYTES>>>(xqh, xql, wqh, wql,
                                                       (float*)0, pqh, pql, 0.125f,
                                                       MTOT, EMBED, EMBED);
    gemm_nt_bf16s_kernel<<<gp, 256, GEMM_SMEM_BYTES>>>(xkh, xkl, wkh, wkl,
                                                       (float*)0, pkh, pkl, 1.0f,
                                                       MTOT, EMBED, EMBED);
    gemm_nt_bf16s_kernel<<<gp, 256, GEMM_SMEM_BYTES>>>(xvh, xvl, wvh, wvl,
                                                       (float*)0, pvh, pvl, 1.0f,
                                                       MTOT, EMBED, EMBED);

    dim3 ga(SQ / 64, NHEAD, BATCH);
    attn_mma_kernel<<<ga, 128, ATTN2_SMEM_BYTES>>>(pqh, pql, pkh, pkl, pvh, pvl,
                                                   bias, aoh, aol);

    gemm_nt_bf16s_kernel<<<gp, 256, GEMM_SMEM_BYTES>>>(aoh, aol, woh, wol,
                                                       out, (__nv_bfloat16*)0,
                                                       (__nv_bfloat16*)0, 1.0f,
                                                       MTOT, EMBED, EMBED);
}